// round 1
// baseline (speedup 1.0000x reference)
#include <cuda_runtime.h>
#include <cuda_bf16.h>

// Problem constants (from reference: past_grid [32, 64, 192, 192] fp32)
#define C_  32
#define D_  64
#define H_  192
#define W_  192
#define HW_  (H_ * W_)            // 36864
#define DHW_ (D_ * HW_)           // 2359296

// Fused affine coefficients: ix/iy/iz = coef[r*4+0]*h + coef[r*4+1]*w + coef[r*4+2]*d + coef[r*4+3]
__device__ float g_coef[12];

// ---------------------------------------------------------------------------
// Setup kernel: fold meshgrid scaling, both pose transforms, the axis reorder
// g[...,[2,0,1]], the [-1,1] normalization by [D,H,W]-1, and the grid_sample
// unnormalization into one 3x4 affine map from (h, w, d) -> (ix, iy, iz).
//
// Reference math:
//   v = ( (h-ch), (w-cw), (d-cd) ) * vox        (vx from h, vy from w, vz from d)
//   p = Rc v + tc
//   q = Rp^T (p - tp)           => q = M v + b,  M = Rp^T Rc,  b = Rp^T (tc - tp)
//   slot0 = q.z/vox, slot1 = q.x/vox, slot2 = q.y/vox
//   n0 = 2*slot0/(D-1), n1 = 2*slot1/(H-1), n2 = 2*slot2/(W-1)
//   ix = ((n0+1)*W - 1)/2   (sampled along W axis)
//   iy = ((n1+1)*H - 1)/2   (along H)
//   iz = ((n2+1)*D - 1)/2   (along D)
// ---------------------------------------------------------------------------
__global__ void setup_kernel(const float* __restrict__ voxp,
                             const float* __restrict__ Rp,
                             const float* __restrict__ tp,
                             const float* __restrict__ Rc,
                             const float* __restrict__ tc) {
    if (threadIdx.x != 0 || blockIdx.x != 0) return;
    double vox = (double)voxp[0];
    double M[3][3], b[3];
    for (int j = 0; j < 3; j++) {
        for (int k = 0; k < 3; k++) {
            double s = 0.0;
            for (int i = 0; i < 3; i++) s += (double)Rp[i*3+j] * (double)Rc[i*3+k];
            M[j][k] = s;
        }
        double sb = 0.0;
        for (int i = 0; i < 3; i++) sb += (double)Rp[i*3+j] * ((double)tc[i] - (double)tp[i]);
        b[j] = sb;
    }
    const double ch = (H_ - 1) * 0.5, cw = (W_ - 1) * 0.5, cd = (D_ - 1) * 0.5;
    // row r: r=0 -> ix (uses q[2], scale W/(vox*(D-1)), offset (W-1)/2)
    //        r=1 -> iy (uses q[0], scale H/(vox*(H-1)), offset (H-1)/2)
    //        r=2 -> iz (uses q[1], scale D/(vox*(W-1)), offset (D-1)/2)
    const int    qi[3] = {2, 0, 1};
    const double A[3]  = { (double)W_ / (vox * (D_ - 1)),
                           (double)H_ / (vox * (H_ - 1)),
                           (double)D_ / (vox * (W_ - 1)) };
    const double Cadd[3] = { (W_ - 1) * 0.5, (H_ - 1) * 0.5, (D_ - 1) * 0.5 };
    for (int r = 0; r < 3; r++) {
        int j = qi[r];
        double mh = M[j][0] * vox;   // multiplies h
        double mw = M[j][1] * vox;   // multiplies w
        double md = M[j][2] * vox;   // multiplies d
        g_coef[r*4 + 0] = (float)(mh * A[r]);
        g_coef[r*4 + 1] = (float)(mw * A[r]);
        g_coef[r*4 + 2] = (float)(md * A[r]);
        g_coef[r*4 + 3] = (float)(A[r] * (b[j] - mh*ch - mw*cw - md*cd) + Cadd[r]);
    }
}

// ---------------------------------------------------------------------------
// Main kernel: one thread per spatial point (d,h,w); loops over 32 channels.
// 8 corner offsets + 8 combined weights computed once; per-axis validity is
// folded into per-axis weights (product == reference's valid conjunction).
// ---------------------------------------------------------------------------
__global__ __launch_bounds__(256)
void sample_kernel(const float* __restrict__ in, float* __restrict__ out) {
    int idx = blockIdx.x * 256 + threadIdx.x;          // 0 .. DHW-1 (exact multiple)
    int w = idx % W_;
    int t = idx / W_;
    int h = t % H_;
    int d = t / H_;

    float fh = (float)h, fw = (float)w, fd = (float)d;
    float c0 = g_coef[0], c1 = g_coef[1], c2  = g_coef[2],  c3  = g_coef[3];
    float c4 = g_coef[4], c5 = g_coef[5], c6  = g_coef[6],  c7  = g_coef[7];
    float c8 = g_coef[8], c9 = g_coef[9], c10 = g_coef[10], c11 = g_coef[11];

    float ix = fmaf(c0, fh, fmaf(c1, fw, fmaf(c2,  fd, c3)));
    float iy = fmaf(c4, fh, fmaf(c5, fw, fmaf(c6,  fd, c7)));
    float iz = fmaf(c8, fh, fmaf(c9, fw, fmaf(c10, fd, c11)));

    float xf = floorf(ix); int x0 = (int)xf; float tx = ix - xf;
    float yf = floorf(iy); int y0 = (int)yf; float ty = iy - yf;
    float zf = floorf(iz); int z0 = (int)zf; float tz = iz - zf;

    // per-axis weights with validity folded in
    float wx0 = (x0 >= 0  && x0 <  W_) ? (1.0f - tx) : 0.0f;
    float wx1 = (x0 >= -1 && x0 <  W_ - 1) ? tx : 0.0f;
    float wy0 = (y0 >= 0  && y0 <  H_) ? (1.0f - ty) : 0.0f;
    float wy1 = (y0 >= -1 && y0 <  H_ - 1) ? ty : 0.0f;
    float wz0 = (z0 >= 0  && z0 <  D_) ? (1.0f - tz) : 0.0f;
    float wz1 = (z0 >= -1 && z0 <  D_ - 1) ? tz : 0.0f;

    // clamped indices
    int xc0 = min(max(x0,     0), W_ - 1);
    int xc1 = min(max(x0 + 1, 0), W_ - 1);
    int yo0 = min(max(y0,     0), H_ - 1) * W_;
    int yo1 = min(max(y0 + 1, 0), H_ - 1) * W_;
    int zo0 = min(max(z0,     0), D_ - 1) * HW_;
    int zo1 = min(max(z0 + 1, 0), D_ - 1) * HW_;

    int o000 = zo0 + yo0 + xc0;
    int o001 = zo0 + yo0 + xc1;
    int o010 = zo0 + yo1 + xc0;
    int o011 = zo0 + yo1 + xc1;
    int o100 = zo1 + yo0 + xc0;
    int o101 = zo1 + yo0 + xc1;
    int o110 = zo1 + yo1 + xc0;
    int o111 = zo1 + yo1 + xc1;

    float W000 = wz0 * wy0 * wx0;
    float W001 = wz0 * wy0 * wx1;
    float W010 = wz0 * wy1 * wx0;
    float W011 = wz0 * wy1 * wx1;
    float W100 = wz1 * wy0 * wx0;
    float W101 = wz1 * wy0 * wx1;
    float W110 = wz1 * wy1 * wx0;
    float W111 = wz1 * wy1 * wx1;

    const float* __restrict__ pin = in;
    float* __restrict__ pout = out + idx;

#pragma unroll 8
    for (int c = 0; c < C_; c++) {
        const float* __restrict__ base = pin + c * DHW_;
        float acc;
        acc =       W000 * __ldg(base + o000);
        acc = fmaf(W001, __ldg(base + o001), acc);
        acc = fmaf(W010, __ldg(base + o010), acc);
        acc = fmaf(W011, __ldg(base + o011), acc);
        acc = fmaf(W100, __ldg(base + o100), acc);
        acc = fmaf(W101, __ldg(base + o101), acc);
        acc = fmaf(W110, __ldg(base + o110), acc);
        acc = fmaf(W111, __ldg(base + o111), acc);
        pout[c * DHW_] = acc;
    }
}

extern "C" void kernel_launch(void* const* d_in, const int* in_sizes, int n_in,
                              void* d_out, int out_size) {
    const float* past_grid = (const float*)d_in[0];
    const float* voxelsize = (const float*)d_in[1];
    const float* rot_past  = (const float*)d_in[2];
    const float* trans_past= (const float*)d_in[3];
    const float* rot_cur   = (const float*)d_in[4];
    const float* trans_cur = (const float*)d_in[5];
    float* out = (float*)d_out;

    setup_kernel<<<1, 1>>>(voxelsize, rot_past, trans_past, rot_cur, trans_cur);
    sample_kernel<<<DHW_ / 256, 256>>>(past_grid, out);
}

// round 3
// speedup vs baseline: 1.3665x; 1.3665x over previous
#include <cuda_runtime.h>
#include <cuda_bf16.h>

// Problem constants (past_grid [32, 64, 192, 192] fp32)
#define C_  32
#define D_  64
#define H_  192
#define W_  192
#define HW_  (H_ * W_)            // 36864
#define DHW_ (D_ * HW_)           // 2359296

// Fused affine coefficients: ix/iy/iz = coef[r*4+0]*h + coef[r*4+1]*w + coef[r*4+2]*d + coef[r*4+3]
__device__ float g_coef[12];

__global__ void setup_kernel(const float* __restrict__ voxp,
                             const float* __restrict__ Rp,
                             const float* __restrict__ tp,
                             const float* __restrict__ Rc,
                             const float* __restrict__ tc) {
    if (threadIdx.x != 0 || blockIdx.x != 0) return;
    double vox = (double)voxp[0];
    double M[3][3], b[3];
    for (int j = 0; j < 3; j++) {
        for (int k = 0; k < 3; k++) {
            double s = 0.0;
            for (int i = 0; i < 3; i++) s += (double)Rp[i*3+j] * (double)Rc[i*3+k];
            M[j][k] = s;
        }
        double sb = 0.0;
        for (int i = 0; i < 3; i++) sb += (double)Rp[i*3+j] * ((double)tc[i] - (double)tp[i]);
        b[j] = sb;
    }
    const double ch = (H_ - 1) * 0.5, cw = (W_ - 1) * 0.5, cd = (D_ - 1) * 0.5;
    const int    qi[3] = {2, 0, 1};
    const double A[3]  = { (double)W_ / (vox * (D_ - 1)),
                           (double)H_ / (vox * (H_ - 1)),
                           (double)D_ / (vox * (W_ - 1)) };
    const double Cadd[3] = { (W_ - 1) * 0.5, (H_ - 1) * 0.5, (D_ - 1) * 0.5 };
    for (int r = 0; r < 3; r++) {
        int j = qi[r];
        double mh = M[j][0] * vox;
        double mw = M[j][1] * vox;
        double md = M[j][2] * vox;
        g_coef[r*4 + 0] = (float)(mh * A[r]);
        g_coef[r*4 + 1] = (float)(mw * A[r]);
        g_coef[r*4 + 2] = (float)(md * A[r]);
        g_coef[r*4 + 3] = (float)(A[r] * (b[j] - mh*ch - mw*cw - md*cd) + Cadd[r]);
    }
}

// ---------------------------------------------------------------------------
// Tile: 32 d x 8 w at fixed h.
// Gather phase: lane = td (d fast) so warp sweeps contiguous input-x
// (ix ~ 3.05*d). Staged in smem with layout addr = c*320 + 9*td + 4*tw:
//   - injective (9*td+4*tw < 320, no 9a=4b collisions in range)
//   - write banks (9*td) mod 32: full permutation (gcd(9,32)=1)
//   - read banks (9*(l>>3) + 4*(l&7)) mod 32: full permutation (checked)
// Store phase: lane -> (dp = tid>>3, wp = tid&7), w fast => 4x32B segments
// per warp-store (sector-optimal).
// ---------------------------------------------------------------------------
__global__ __launch_bounds__(256)
void sample_kernel(const float* __restrict__ in, float* __restrict__ out) {
    __shared__ float sbuf[10228];  // 31*320 + 9*31 + 4*7 + 1 floats = ~40 KB

    const int tid = threadIdx.x;
    const int td  = tid & 31;      // d within tile (fast within warp)
    const int tw  = tid >> 5;      // w within tile (0..7)

    const int d = blockIdx.z * 32 + td;
    const int h = blockIdx.y;
    const int w = blockIdx.x * 8 + tw;

    const float fh = (float)h, fw = (float)w, fd = (float)d;
    const float c0 = g_coef[0], c1 = g_coef[1], c2  = g_coef[2],  c3  = g_coef[3];
    const float c4 = g_coef[4], c5 = g_coef[5], c6  = g_coef[6],  c7  = g_coef[7];
    const float c8 = g_coef[8], c9 = g_coef[9], c10 = g_coef[10], c11 = g_coef[11];

    const float ix = fmaf(c0, fh, fmaf(c1, fw, fmaf(c2,  fd, c3)));
    const float iy = fmaf(c4, fh, fmaf(c5, fw, fmaf(c6,  fd, c7)));
    const float iz = fmaf(c8, fh, fmaf(c9, fw, fmaf(c10, fd, c11)));

    const float xf = floorf(ix); const int x0 = (int)xf; const float tx = ix - xf;
    const float yf = floorf(iy); const int y0 = (int)yf; const float ty = iy - yf;
    const float zf = floorf(iz); const int z0 = (int)zf; const float tz = iz - zf;

    const float wx0 = (x0 >= 0  && x0 <  W_)     ? (1.0f - tx) : 0.0f;
    const float wx1 = (x0 >= -1 && x0 <  W_ - 1) ? tx          : 0.0f;
    const float wy0 = (y0 >= 0  && y0 <  H_)     ? (1.0f - ty) : 0.0f;
    const float wy1 = (y0 >= -1 && y0 <  H_ - 1) ? ty          : 0.0f;
    const float wz0 = (z0 >= 0  && z0 <  D_)     ? (1.0f - tz) : 0.0f;
    const float wz1 = (z0 >= -1 && z0 <  D_ - 1) ? tz          : 0.0f;

    const int xc0 = min(max(x0,     0), W_ - 1);
    const int xc1 = min(max(x0 + 1, 0), W_ - 1);
    const int yo0 = min(max(y0,     0), H_ - 1) * W_;
    const int yo1 = min(max(y0 + 1, 0), H_ - 1) * W_;
    const int zo0 = min(max(z0,     0), D_ - 1) * HW_;
    const int zo1 = min(max(z0 + 1, 0), D_ - 1) * HW_;

    const int o000 = zo0 + yo0 + xc0;
    const int o001 = zo0 + yo0 + xc1;
    const int o010 = zo0 + yo1 + xc0;
    const int o011 = zo0 + yo1 + xc1;
    const int o100 = zo1 + yo0 + xc0;
    const int o101 = zo1 + yo0 + xc1;
    const int o110 = zo1 + yo1 + xc0;
    const int o111 = zo1 + yo1 + xc1;

    const float W000 = wz0 * wy0 * wx0;
    const float W001 = wz0 * wy0 * wx1;
    const float W010 = wz0 * wy1 * wx0;
    const float W011 = wz0 * wy1 * wx1;
    const float W100 = wz1 * wy0 * wx0;
    const float W101 = wz1 * wy0 * wx1;
    const float W110 = wz1 * wy1 * wx0;
    const float W111 = wz1 * wy1 * wx1;

    float* sp = sbuf + 9 * td + 4 * tw;   // + c*320 in loop

#pragma unroll 4
    for (int c = 0; c < C_; c++) {
        const float* __restrict__ base = in + (size_t)c * DHW_;
        float acc;
        acc =       W000 * __ldg(base + o000);
        acc = fmaf(W001, __ldg(base + o001), acc);
        acc = fmaf(W010, __ldg(base + o010), acc);
        acc = fmaf(W011, __ldg(base + o011), acc);
        acc = fmaf(W100, __ldg(base + o100), acc);
        acc = fmaf(W101, __ldg(base + o101), acc);
        acc = fmaf(W110, __ldg(base + o110), acc);
        acc = fmaf(W111, __ldg(base + o111), acc);
        sp[c * 320] = acc;
    }

    __syncthreads();

    // Store phase: tid -> (d' = tid>>3, w' = tid&7)
    const int dp = tid >> 3;
    const int wp = tid & 7;
    const float* rp = sbuf + 9 * dp + 4 * wp;
    const size_t ob = (size_t)(blockIdx.z * 32 + dp) * HW_
                    + (size_t)h * W_ + blockIdx.x * 8 + wp;
    float* __restrict__ po = out + ob;

#pragma unroll
    for (int c = 0; c < C_; c++) {
        po[(size_t)c * DHW_] = rp[c * 320];
    }
}

extern "C" void kernel_launch(void* const* d_in, const int* in_sizes, int n_in,
                              void* d_out, int out_size) {
    const float* past_grid  = (const float*)d_in[0];
    const float* voxelsize  = (const float*)d_in[1];
    const float* rot_past   = (const float*)d_in[2];
    const float* trans_past = (const float*)d_in[3];
    const float* rot_cur    = (const float*)d_in[4];
    const float* trans_cur  = (const float*)d_in[5];
    float* out = (float*)d_out;

    setup_kernel<<<1, 1>>>(voxelsize, rot_past, trans_past, rot_cur, trans_cur);

    dim3 grid(W_ / 8, H_, D_ / 32);   // 24 x 192 x 2 = 9216 blocks
    sample_kernel<<<grid, 256>>>(past_grid, out);
}